// round 3
// baseline (speedup 1.0000x reference)
#include <cuda_runtime.h>

static constexpr int BATCH = 8;
static constexpr int SEQ   = 16384;
static constexpr int CH    = 256;
static constexpr int TOPN  = 2048;
static constexpr int ROWS  = BATCH * SEQ;              // 131072
static constexpr int ROWS_PER_BLOCK = 64;              // 16 warps * 4 rows
static constexpr int K1_BLOCKS = ROWS / ROWS_PER_BLOCK;  // 2048

__device__ float g_score[ROWS];
__device__ float g_psum[K1_BLOCKS];
__device__ float g_psq[K1_BLOCKS];
__device__ unsigned g_idx[BATCH * TOPN];

// ---------------------------------------------------------------------------
// K1: score[row] = dot(x_in[row,:], w) + b.  4 rows per warp -> 8 independent
// 128B loads in flight per thread, streaming (read-once data).
// ---------------------------------------------------------------------------
__global__ __launch_bounds__(512) void score_kernel(const float* __restrict__ x,
                                                    const float* __restrict__ w,
                                                    const float* __restrict__ bias) {
    const int warp = threadIdx.x >> 5;
    const int lane = threadIdx.x & 31;
    const size_t r0 = ((size_t)blockIdx.x * 16 + warp) * 4;

    const float4* xr = (const float4*)(x + r0 * CH);   // row stride = 64 float4
    const float4* wv = (const float4*)w;

    float4 a[8];
#pragma unroll
    for (int r = 0; r < 4; r++) {
        a[2*r]   = __ldcs(xr + r * 64 + lane);
        a[2*r+1] = __ldcs(xr + r * 64 + 32 + lane);
    }
    float4 w0 = wv[lane];
    float4 w1 = wv[lane + 32];

    float s[4];
#pragma unroll
    for (int r = 0; r < 4; r++) {
        float4 p = a[2*r], q = a[2*r+1];
        s[r] = p.x*w0.x + p.y*w0.y + p.z*w0.z + p.w*w0.w
             + q.x*w1.x + q.y*w1.y + q.z*w1.z + q.w*w1.w;
    }
#pragma unroll
    for (int off = 16; off > 0; off >>= 1)
#pragma unroll
        for (int r = 0; r < 4; r++)
            s[r] += __shfl_xor_sync(0xffffffffu, s[r], off);

    __shared__ float ws[ROWS_PER_BLOCK], wq[ROWS_PER_BLOCK];
    if (lane == 0) {
        float bb = bias[0];
#pragma unroll
        for (int r = 0; r < 4; r++) {
            float c = s[r] + bb;
            g_score[r0 + r] = c;
            ws[warp*4 + r] = c;
            wq[warp*4 + r] = c * c;
        }
    }
    __syncthreads();
    if (threadIdx.x < 32) {
        float S = ws[threadIdx.x] + ws[threadIdx.x + 32];
        float Q = wq[threadIdx.x] + wq[threadIdx.x + 32];
#pragma unroll
        for (int off = 16; off > 0; off >>= 1) {
            S += __shfl_xor_sync(0xffffffffu, S, off);
            Q += __shfl_xor_sync(0xffffffffu, Q, off);
        }
        if (threadIdx.x == 0) { g_psum[blockIdx.x] = S; g_psq[blockIdx.x] = Q; }
    }
}

// ---------------------------------------------------------------------------
// Bitonic helper: register compare-exchange via shfl (j <= 16)
// ---------------------------------------------------------------------------
__device__ __forceinline__ unsigned long long cex_shfl(unsigned long long E,
                                                       int i, int j, int k) {
    unsigned long long P = __shfl_xor_sync(0xffffffffu, E, j);
    bool takeMin = (((i & j) == 0) == ((i & k) == 0));
    if (takeMin ? (P < E) : (P > E)) E = P;
    return E;
}

// ---------------------------------------------------------------------------
// K2: one CTA per batch. Stable top-TOPN-smallest via 46-bit keys
// (bits(relu(normalized)) << 14) | index. 6-pass radix-select of rank
// (TOPN-1) with match-aggregated histogram atomics, ballot-aggregated
// collect, then hybrid (smem + shfl) bitonic sort of the TOPN keys.
// ---------------------------------------------------------------------------
__global__ __launch_bounds__(1024) void select_kernel(const float* __restrict__ gamma,
                                                      const float* __restrict__ beta) {
    extern __shared__ unsigned long long dyn[];
    unsigned long long* keys = dyn;          // SEQ
    unsigned long long* sel  = dyn + SEQ;    // TOPN

    __shared__ unsigned hist[256];
    __shared__ float red1[1024], red2[1024];
    __shared__ unsigned long long prefix_s;
    __shared__ int k_s;
    __shared__ unsigned cnt_s;

    const int tid  = threadIdx.x;
    const int lane = tid & 31;
    const int b    = blockIdx.x;

    // --- mean / var from K1 partials ---
    float S = 0.f, Q = 0.f;
    for (int i = tid; i < K1_BLOCKS; i += 1024) { S += g_psum[i]; Q += g_psq[i]; }
    red1[tid] = S; red2[tid] = Q;
    __syncthreads();
    for (int off = 512; off > 0; off >>= 1) {
        if (tid < off) { red1[tid] += red1[tid + off]; red2[tid] += red2[tid + off]; }
        __syncthreads();
    }
    float mean = red1[0] / (float)ROWS;
    float var  = red2[0] / (float)ROWS - mean * mean;
    if (var < 0.f) var = 0.f;
    float scale = rsqrtf(var + 1e-5f) * gamma[0];
    float shift = beta[0] - mean * scale;

    // --- build 46-bit keys ---
    const float* sc = g_score + (size_t)b * SEQ;
    for (int i = tid; i < SEQ; i += 1024) {
        float r = fmaxf(0.f, fmaf(sc[i], scale, shift));   // >= +0
        keys[i] = ((unsigned long long)__float_as_uint(r) << 14) | (unsigned)i;
    }
    if (tid == 0) { prefix_s = 0ULL; k_s = TOPN - 1; cnt_s = 0u; }
    __syncthreads();

    // --- radix-select rank TOPN-1 over 6 byte-digits (bits 40..0) ---
    unsigned long long prefix = 0ULL;
#pragma unroll
    for (int d = 5; d >= 0; --d) {
        for (int i = tid; i < 256; i += 1024) hist[i] = 0u;
        __syncthreads();
        const int sh = d * 8;
        const unsigned long long pmask = (d == 5) ? 0ULL : (~0ULL << (sh + 8));
        for (int i = tid; i < SEQ; i += 1024) {
            unsigned long long key = keys[i];
            bool p = ((key & pmask) == prefix);
            unsigned active = __ballot_sync(0xffffffffu, p);
            if (p) {
                unsigned bin = (unsigned)(key >> sh) & 255u;
                unsigned peers = __match_any_sync(active, bin);
                if (lane == __ffs(peers) - 1)
                    atomicAdd(&hist[bin], __popc(peers));
            }
        }
        __syncthreads();
        if (tid < 32) {
            int k = k_s;
            unsigned v[8]; unsigned tot = 0u;
#pragma unroll
            for (int j = 0; j < 8; j++) { v[j] = hist[tid*8 + j]; tot += v[j]; }
            unsigned ex = tot;
#pragma unroll
            for (int off = 1; off < 32; off <<= 1) {
                unsigned n = __shfl_up_sync(0xffffffffu, ex, off);
                if (tid >= off) ex += n;
            }
            ex -= tot;
            if ((unsigned)k >= ex && (unsigned)k < ex + tot) {
                unsigned kk = (unsigned)k - ex;
                int bin = tid * 8;
#pragma unroll
                for (int j = 0; j < 8; j++) {
                    if (kk < v[j]) { bin = tid*8 + j; break; }
                    kk -= v[j];
                }
                prefix_s = prefix | ((unsigned long long)bin << sh);
                k_s = (int)kk;
            }
        }
        __syncthreads();
        prefix = prefix_s;
    }
    const unsigned long long cutoff = prefix;   // exactly TOPN keys <= cutoff

    // --- collect selected keys (ballot-aggregated) ---
    for (int i = tid; i < SEQ; i += 1024) {
        unsigned long long key = keys[i];
        bool p = (key <= cutoff);
        unsigned m = __ballot_sync(0xffffffffu, p);
        if (p) {
            int leader = __ffs(m) - 1;
            unsigned base;
            if (lane == leader) base = atomicAdd(&cnt_s, (unsigned)__popc(m));
            base = __shfl_sync(m, base, leader);
            sel[base + __popc(m & ((1u << lane) - 1u))] = key;
        }
    }
    __syncthreads();

    // --- hybrid bitonic sort of TOPN=2048 keys, ascending ---
    // thread t owns elements t (E0) and t+1024 (E1)
    unsigned long long E0 = sel[tid];
    unsigned long long E1 = sel[tid + 1024];

    // k = 2..32 : pure shfl stages
#pragma unroll
    for (int k = 2; k <= 32; k <<= 1)
#pragma unroll
        for (int j = k >> 1; j >= 1; j >>= 1) {
            E0 = cex_shfl(E0, tid, j, k);
            E1 = cex_shfl(E1, tid + 1024, j, k);
        }

    // k = 64..1024 : smem stages (j>=32) then shfl stages (j<=16)
#pragma unroll
    for (int k = 64; k <= 1024; k <<= 1) {
        __syncthreads();
        sel[tid] = E0; sel[tid + 1024] = E1;
        __syncthreads();
        for (int j = k >> 1; j >= 32; j >>= 1) {
            int idx = ((tid & ~(j - 1)) << 1) | (tid & (j - 1));
            int l = idx | j;
            unsigned long long a = sel[idx], c = sel[l];
            bool asc = ((idx & k) == 0);
            if ((a > c) == asc) { sel[idx] = c; sel[l] = a; }
            __syncthreads();
        }
        E0 = sel[tid]; E1 = sel[tid + 1024];
#pragma unroll
        for (int j = 16; j >= 1; j >>= 1) {
            E0 = cex_shfl(E0, tid, j, k);
            E1 = cex_shfl(E1, tid + 1024, j, k);
        }
    }

    // k = 2048 : j=1024 is the in-register pair; then smem; then shfl
    {
        const int k = 2048;
        if (E0 > E1) { unsigned long long t = E0; E0 = E1; E1 = t; }  // asc
        __syncthreads();
        sel[tid] = E0; sel[tid + 1024] = E1;
        __syncthreads();
        for (int j = 512; j >= 32; j >>= 1) {
            int idx = ((tid & ~(j - 1)) << 1) | (tid & (j - 1));
            int l = idx | j;
            unsigned long long a = sel[idx], c = sel[l];
            if (a > c) { sel[idx] = c; sel[l] = a; }   // asc==true for k=2048
            __syncthreads();
        }
        E0 = sel[tid]; E1 = sel[tid + 1024];
#pragma unroll
        for (int j = 16; j >= 1; j >>= 1) {
            E0 = cex_shfl(E0, tid, j, k);
            E1 = cex_shfl(E1, tid + 1024, j, k);
        }
    }

    g_idx[b * TOPN + tid]        = (unsigned)(E0 & 0x3fffu);
    g_idx[b * TOPN + tid + 1024] = (unsigned)(E1 & 0x3fffu);
}

// ---------------------------------------------------------------------------
// K3: gather rows: out[b, r, :] = x_select[b, idx[b,r], :]
// ---------------------------------------------------------------------------
__global__ __launch_bounds__(256) void gather_kernel(const float* __restrict__ xs,
                                                     float* __restrict__ out) {
    int rid  = blockIdx.x * 4 + (threadIdx.x >> 6);
    int lane = threadIdx.x & 63;
    int b    = rid >> 11;
    unsigned idx = g_idx[rid];
    const float4* src = (const float4*)(xs + ((size_t)b * SEQ + idx) * CH);
    float4* dst = (float4*)(out + (size_t)rid * CH);
    dst[lane] = src[lane];
}

// ---------------------------------------------------------------------------
extern "C" void kernel_launch(void* const* d_in, const int* in_sizes, int n_in,
                              void* d_out, int out_size) {
    const float* x_in  = (const float*)d_in[0];
    const float* x_sel = (const float*)d_in[1];
    const float* w     = (const float*)d_in[2];
    const float* bias  = (const float*)d_in[3];
    const float* gamma = (const float*)d_in[4];
    const float* beta  = (const float*)d_in[5];
    float* out = (float*)d_out;

    const int sel_smem = (SEQ + TOPN) * (int)sizeof(unsigned long long);  // 147456
    cudaFuncSetAttribute(select_kernel,
                         cudaFuncAttributeMaxDynamicSharedMemorySize, sel_smem);

    score_kernel<<<K1_BLOCKS, 512>>>(x_in, w, bias);
    select_kernel<<<BATCH, 1024, sel_smem>>>(gamma, beta);
    gather_kernel<<<(BATCH * TOPN) / 4, 256>>>(x_sel, out);
}

// round 4
// speedup vs baseline: 1.4127x; 1.4127x over previous
#include <cuda_runtime.h>

static constexpr int BATCH = 8;
static constexpr int SEQ   = 16384;
static constexpr int CH    = 256;
static constexpr int TOPN  = 2048;
static constexpr int ROWS  = BATCH * SEQ;                 // 131072
static constexpr int ROWS_PER_BLOCK = 32;                 // 16 warps * 2 rows
static constexpr int K1_BLOCKS = ROWS / ROWS_PER_BLOCK;   // 4096

__device__ float g_score[ROWS];
__device__ float g_psum[K1_BLOCKS];
__device__ float g_psq[K1_BLOCKS];
__device__ unsigned g_idx[BATCH * TOPN];

// ---------------------------------------------------------------------------
// K1: score[row] = dot(x_in[row,:], w) + b.  Two rows per warp (R1 config —
// best measured DRAM utilization), streaming loads.
// ---------------------------------------------------------------------------
__global__ __launch_bounds__(512) void score_kernel(const float* __restrict__ x,
                                                    const float* __restrict__ w,
                                                    const float* __restrict__ bias) {
    int warp = threadIdx.x >> 5;
    int lane = threadIdx.x & 31;
    size_t r0 = (size_t)blockIdx.x * ROWS_PER_BLOCK + warp * 2;

    const float4* x0 = (const float4*)(x + r0 * CH);
    const float4* x1 = (const float4*)(x + (r0 + 1) * CH);
    const float4* wv = (const float4*)w;

    float4 a0 = __ldcs(x0 + lane);
    float4 a1 = __ldcs(x0 + lane + 32);
    float4 b0 = __ldcs(x1 + lane);
    float4 b1 = __ldcs(x1 + lane + 32);
    float4 w0 = wv[lane];
    float4 w1 = wv[lane + 32];

    float s0 = a0.x*w0.x + a0.y*w0.y + a0.z*w0.z + a0.w*w0.w
             + a1.x*w1.x + a1.y*w1.y + a1.z*w1.z + a1.w*w1.w;
    float s1 = b0.x*w0.x + b0.y*w0.y + b0.z*w0.z + b0.w*w0.w
             + b1.x*w1.x + b1.y*w1.y + b1.z*w1.z + b1.w*w1.w;
#pragma unroll
    for (int off = 16; off > 0; off >>= 1) {
        s0 += __shfl_xor_sync(0xffffffffu, s0, off);
        s1 += __shfl_xor_sync(0xffffffffu, s1, off);
    }

    __shared__ float ws[ROWS_PER_BLOCK], wq[ROWS_PER_BLOCK];
    if (lane == 0) {
        float bb = bias[0];
        float c0 = s0 + bb, c1 = s1 + bb;
        g_score[r0]     = c0;
        g_score[r0 + 1] = c1;
        ws[warp*2]   = c0;  wq[warp*2]   = c0*c0;
        ws[warp*2+1] = c1;  wq[warp*2+1] = c1*c1;
    }
    __syncthreads();
    if (threadIdx.x < 32) {
        float S = ws[threadIdx.x];
        float Q = wq[threadIdx.x];
#pragma unroll
        for (int off = 16; off > 0; off >>= 1) {
            S += __shfl_xor_sync(0xffffffffu, S, off);
            Q += __shfl_xor_sync(0xffffffffu, Q, off);
        }
        if (threadIdx.x == 0) { g_psum[blockIdx.x] = S; g_psq[blockIdx.x] = Q; }
    }
}

// ---------------------------------------------------------------------------
// Bitonic helper for the (practically never taken) slow path
// ---------------------------------------------------------------------------
__device__ __forceinline__ unsigned long long cex_shfl(unsigned long long E,
                                                       int i, int j, int k) {
    unsigned long long P = __shfl_xor_sync(0xffffffffu, E, j);
    bool takeMin = (((i & j) == 0) == ((i & k) == 0));
    if (takeMin ? (P < E) : (P > E)) E = P;
    return E;
}

// ---------------------------------------------------------------------------
// K2: one CTA per batch.
// ReLU clamps all normalized scores <= 0 to exactly 0.0; stable ascending
// argsort therefore puts those indices first, in index order. If a batch has
// >= TOPN such elements (always, for N(0,1) data), the answer is a stable
// stream compaction of the first TOPN qualifying indices. Fallback: full
// radix-select + bitonic sort on 46-bit (value,index) keys.
// ---------------------------------------------------------------------------
__global__ __launch_bounds__(1024) void select_kernel(const float* __restrict__ gamma,
                                                      const float* __restrict__ beta) {
    extern __shared__ unsigned long long dyn[];   // used by slow path only
    unsigned long long* keys = dyn;               // SEQ
    unsigned long long* sel  = dyn + SEQ;         // TOPN

    __shared__ float red1[1024], red2[1024];
    __shared__ unsigned warpsum[32];
    __shared__ unsigned warpexcl[32];
    __shared__ unsigned total_s;

    const int tid  = threadIdx.x;
    const int lane = tid & 31;
    const int warp = tid >> 5;
    const int b    = blockIdx.x;

    // --- mean / var from K1 partials ---
    float S = 0.f, Q = 0.f;
    for (int i = tid; i < K1_BLOCKS; i += 1024) { S += g_psum[i]; Q += g_psq[i]; }
    red1[tid] = S; red2[tid] = Q;
    __syncthreads();
    for (int off = 512; off > 0; off >>= 1) {
        if (tid < off) { red1[tid] += red1[tid + off]; red2[tid] += red2[tid + off]; }
        __syncthreads();
    }
    float mean = red1[0] / (float)ROWS;
    float var  = red2[0] / (float)ROWS - mean * mean;
    if (var < 0.f) var = 0.f;
    float scale = rsqrtf(var + 1e-5f) * gamma[0];
    float shift = beta[0] - mean * scale;

    // --- fast path: stable compaction of normalized <= 0 (relu == 0) ---
    // thread t owns contiguous chunk [t*16, t*16+16)
    const float* sc = g_score + (size_t)b * SEQ;
    const float4* p4 = (const float4*)(sc + tid * 16);
    unsigned mask16 = 0;
#pragma unroll
    for (int j = 0; j < 4; j++) {
        float4 v = p4[j];
        if (fmaf(v.x, scale, shift) <= 0.f) mask16 |= 1u << (4*j + 0);
        if (fmaf(v.y, scale, shift) <= 0.f) mask16 |= 1u << (4*j + 1);
        if (fmaf(v.z, scale, shift) <= 0.f) mask16 |= 1u << (4*j + 2);
        if (fmaf(v.w, scale, shift) <= 0.f) mask16 |= 1u << (4*j + 3);
    }
    unsigned c = (unsigned)__popc(mask16);

    // warp inclusive scan of c
    unsigned incl = c;
#pragma unroll
    for (int off = 1; off < 32; off <<= 1) {
        unsigned n = __shfl_up_sync(0xffffffffu, incl, off);
        if (lane >= off) incl += n;
    }
    if (lane == 31) warpsum[warp] = incl;
    __syncthreads();
    if (tid < 32) {
        unsigned wv = warpsum[tid];
        unsigned wincl = wv;
#pragma unroll
        for (int off = 1; off < 32; off <<= 1) {
            unsigned n = __shfl_up_sync(0xffffffffu, wincl, off);
            if (tid >= off) wincl += n;
        }
        warpexcl[tid] = wincl - wv;
        if (tid == 31) total_s = wincl;
    }
    __syncthreads();
    unsigned T = total_s;

    if (T >= (unsigned)TOPN) {
        unsigned r = warpexcl[warp] + (incl - c);   // exclusive global rank
        if (r < (unsigned)TOPN) {
            unsigned base_i = (unsigned)tid * 16u;
#pragma unroll
            for (int j = 0; j < 16; j++) {
                if (mask16 & (1u << j)) {
                    if (r < (unsigned)TOPN) g_idx[b * TOPN + r] = base_i + j;
                    r++;
                }
            }
        }
        return;
    }

    // =======================================================================
    // Slow path (T < TOPN): full stable top-TOPN via 46-bit keys,
    // radix-select + hybrid bitonic sort. Practically unreachable.
    // =======================================================================
    __shared__ unsigned hist[256];
    __shared__ unsigned long long prefix_s;
    __shared__ int k_s;
    __shared__ unsigned cnt_s;

    for (int i = tid; i < SEQ; i += 1024) {
        float r = fmaxf(0.f, fmaf(sc[i], scale, shift));
        keys[i] = ((unsigned long long)__float_as_uint(r) << 14) | (unsigned)i;
    }
    if (tid == 0) { prefix_s = 0ULL; k_s = TOPN - 1; cnt_s = 0u; }
    __syncthreads();

    unsigned long long prefix = 0ULL;
#pragma unroll
    for (int d = 5; d >= 0; --d) {
        for (int i = tid; i < 256; i += 1024) hist[i] = 0u;
        __syncthreads();
        const int sh = d * 8;
        const unsigned long long pmask = (d == 5) ? 0ULL : (~0ULL << (sh + 8));
        for (int i = tid; i < SEQ; i += 1024) {
            unsigned long long key = keys[i];
            bool pr = ((key & pmask) == prefix);
            unsigned active = __ballot_sync(0xffffffffu, pr);
            if (pr) {
                unsigned bin = (unsigned)(key >> sh) & 255u;
                unsigned peers = __match_any_sync(active, bin);
                if (lane == __ffs(peers) - 1)
                    atomicAdd(&hist[bin], __popc(peers));
            }
        }
        __syncthreads();
        if (tid < 32) {
            int k = k_s;
            unsigned v[8]; unsigned tot = 0u;
#pragma unroll
            for (int j = 0; j < 8; j++) { v[j] = hist[tid*8 + j]; tot += v[j]; }
            unsigned ex = tot;
#pragma unroll
            for (int off = 1; off < 32; off <<= 1) {
                unsigned n = __shfl_up_sync(0xffffffffu, ex, off);
                if (tid >= off) ex += n;
            }
            ex -= tot;
            if ((unsigned)k >= ex && (unsigned)k < ex + tot) {
                unsigned kk = (unsigned)k - ex;
                int bin = tid * 8;
#pragma unroll
                for (int j = 0; j < 8; j++) {
                    if (kk < v[j]) { bin = tid*8 + j; break; }
                    kk -= v[j];
                }
                prefix_s = prefix | ((unsigned long long)bin << sh);
                k_s = (int)kk;
            }
        }
        __syncthreads();
        prefix = prefix_s;
    }
    const unsigned long long cutoff = prefix;

    for (int i = tid; i < SEQ; i += 1024) {
        unsigned long long key = keys[i];
        bool pr = (key <= cutoff);
        unsigned m = __ballot_sync(0xffffffffu, pr);
        if (pr) {
            int leader = __ffs(m) - 1;
            unsigned base;
            if (lane == leader) base = atomicAdd(&cnt_s, (unsigned)__popc(m));
            base = __shfl_sync(m, base, leader);
            sel[base + __popc(m & ((1u << lane) - 1u))] = key;
        }
    }
    __syncthreads();

    unsigned long long E0 = sel[tid];
    unsigned long long E1 = sel[tid + 1024];
#pragma unroll
    for (int k = 2; k <= 32; k <<= 1)
#pragma unroll
        for (int j = k >> 1; j >= 1; j >>= 1) {
            E0 = cex_shfl(E0, tid, j, k);
            E1 = cex_shfl(E1, tid + 1024, j, k);
        }
#pragma unroll
    for (int k = 64; k <= 1024; k <<= 1) {
        __syncthreads();
        sel[tid] = E0; sel[tid + 1024] = E1;
        __syncthreads();
        for (int j = k >> 1; j >= 32; j >>= 1) {
            int idx = ((tid & ~(j - 1)) << 1) | (tid & (j - 1));
            int l = idx | j;
            unsigned long long a = sel[idx], cc = sel[l];
            bool asc = ((idx & k) == 0);
            if ((a > cc) == asc) { sel[idx] = cc; sel[l] = a; }
            __syncthreads();
        }
        E0 = sel[tid]; E1 = sel[tid + 1024];
#pragma unroll
        for (int j = 16; j >= 1; j >>= 1) {
            E0 = cex_shfl(E0, tid, j, k);
            E1 = cex_shfl(E1, tid + 1024, j, k);
        }
    }
    {
        const int k = 2048;
        if (E0 > E1) { unsigned long long t = E0; E0 = E1; E1 = t; }
        __syncthreads();
        sel[tid] = E0; sel[tid + 1024] = E1;
        __syncthreads();
        for (int j = 512; j >= 32; j >>= 1) {
            int idx = ((tid & ~(j - 1)) << 1) | (tid & (j - 1));
            int l = idx | j;
            unsigned long long a = sel[idx], cc = sel[l];
            if (a > cc) { sel[idx] = cc; sel[l] = a; }
            __syncthreads();
        }
        E0 = sel[tid]; E1 = sel[tid + 1024];
#pragma unroll
        for (int j = 16; j >= 1; j >>= 1) {
            E0 = cex_shfl(E0, tid, j, k);
            E1 = cex_shfl(E1, tid + 1024, j, k);
        }
    }
    g_idx[b * TOPN + tid]        = (unsigned)(E0 & 0x3fffu);
    g_idx[b * TOPN + tid + 1024] = (unsigned)(E1 & 0x3fffu);
}

// ---------------------------------------------------------------------------
// K3: gather rows: out[b, r, :] = x_select[b, idx[b,r], :]
// ---------------------------------------------------------------------------
__global__ __launch_bounds__(256) void gather_kernel(const float* __restrict__ xs,
                                                     float* __restrict__ out) {
    int rid  = blockIdx.x * 4 + (threadIdx.x >> 6);
    int lane = threadIdx.x & 63;
    int b    = rid >> 11;
    unsigned idx = g_idx[rid];
    const float4* src = (const float4*)(xs + ((size_t)b * SEQ + idx) * CH);
    float4* dst = (float4*)(out + (size_t)rid * CH);
    dst[lane] = __ldcs(src + lane);
}

// ---------------------------------------------------------------------------
extern "C" void kernel_launch(void* const* d_in, const int* in_sizes, int n_in,
                              void* d_out, int out_size) {
    const float* x_in  = (const float*)d_in[0];
    const float* x_sel = (const float*)d_in[1];
    const float* w     = (const float*)d_in[2];
    const float* bias  = (const float*)d_in[3];
    const float* gamma = (const float*)d_in[4];
    const float* beta  = (const float*)d_in[5];
    float* out = (float*)d_out;

    const int sel_smem = (SEQ + TOPN) * (int)sizeof(unsigned long long);  // 147456
    cudaFuncSetAttribute(select_kernel,
                         cudaFuncAttributeMaxDynamicSharedMemorySize, sel_smem);

    score_kernel<<<K1_BLOCKS, 512>>>(x_in, w, bias);
    select_kernel<<<BATCH, 1024, sel_smem>>>(gamma, beta);
    gather_kernel<<<(BATCH * TOPN) / 4, 256>>>(x_sel, out);
}

// round 5
// speedup vs baseline: 1.6221x; 1.1482x over previous
#include <cuda_runtime.h>

static constexpr int BATCH = 8;
static constexpr int SEQ   = 16384;
static constexpr int CH    = 256;
static constexpr int TOPN  = 2048;
static constexpr int ROWS  = BATCH * SEQ;     // 131072
static constexpr int PAIRS = ROWS / 2;        // 65536

static constexpr int K1_GRID    = 444;        // 148 SMs * 3 resident CTAs
static constexpr int K1_THREADS = 512;        // 16 warps
static constexpr int K1_WARPS_TOTAL = K1_GRID * (K1_THREADS / 32);  // 7104

__device__ float g_score[ROWS];
__device__ float g_psum[K1_GRID];
__device__ float g_psq[K1_GRID];
__device__ unsigned g_idx[BATCH * TOPN];

// ---------------------------------------------------------------------------
// K1: persistent grid-stride. Each warp processes 2 rows per iteration
// (4 independent 128B streaming loads), accumulates sum/sumsq locally,
// reduces once per CTA at the end. Single wave -> no tail.
// ---------------------------------------------------------------------------
__global__ __launch_bounds__(K1_THREADS) void score_kernel(const float* __restrict__ x,
                                                           const float* __restrict__ w,
                                                           const float* __restrict__ bias) {
    const int warp = threadIdx.x >> 5;
    const int lane = threadIdx.x & 31;
    const int gw   = blockIdx.x * (K1_THREADS / 32) + warp;

    const float4* wv = (const float4*)w;
    const float4 w0 = wv[lane];
    const float4 w1 = wv[lane + 32];
    const float bb = bias[0];

    float S = 0.f, Q = 0.f;

#pragma unroll 2
    for (int pair = gw; pair < PAIRS; pair += K1_WARPS_TOTAL) {
        const size_t r0 = (size_t)pair * 2;
        const float4* x0 = (const float4*)(x + r0 * CH);   // 2 rows = 128 float4
        float4 a0 = __ldcs(x0 + lane);
        float4 a1 = __ldcs(x0 + 32 + lane);
        float4 b0 = __ldcs(x0 + 64 + lane);
        float4 b1 = __ldcs(x0 + 96 + lane);

        float s0 = a0.x*w0.x + a0.y*w0.y + a0.z*w0.z + a0.w*w0.w
                 + a1.x*w1.x + a1.y*w1.y + a1.z*w1.z + a1.w*w1.w;
        float s1 = b0.x*w0.x + b0.y*w0.y + b0.z*w0.z + b0.w*w0.w
                 + b1.x*w1.x + b1.y*w1.y + b1.z*w1.z + b1.w*w1.w;
#pragma unroll
        for (int off = 16; off > 0; off >>= 1) {
            s0 += __shfl_xor_sync(0xffffffffu, s0, off);
            s1 += __shfl_xor_sync(0xffffffffu, s1, off);
        }
        if (lane == 0) {
            float c0 = s0 + bb, c1 = s1 + bb;
            __stcs(&g_score[r0],     c0);
            __stcs(&g_score[r0 + 1], c1);
            S += c0 + c1;
            Q += c0*c0 + c1*c1;
        }
    }

    __shared__ float ws[K1_THREADS / 32], wq[K1_THREADS / 32];
    if (lane == 0) { ws[warp] = S; wq[warp] = Q; }
    __syncthreads();
    if (threadIdx.x < 32) {
        float s = (threadIdx.x < K1_THREADS / 32) ? ws[threadIdx.x] : 0.f;
        float q = (threadIdx.x < K1_THREADS / 32) ? wq[threadIdx.x] : 0.f;
#pragma unroll
        for (int off = 16; off > 0; off >>= 1) {
            s += __shfl_xor_sync(0xffffffffu, s, off);
            q += __shfl_xor_sync(0xffffffffu, q, off);
        }
        if (threadIdx.x == 0) { g_psum[blockIdx.x] = s; g_psq[blockIdx.x] = q; }
    }
}

// ---------------------------------------------------------------------------
// Bitonic helper for the (practically never taken) slow path
// ---------------------------------------------------------------------------
__device__ __forceinline__ unsigned long long cex_shfl(unsigned long long E,
                                                       int i, int j, int k) {
    unsigned long long P = __shfl_xor_sync(0xffffffffu, E, j);
    bool takeMin = (((i & j) == 0) == ((i & k) == 0));
    if (takeMin ? (P < E) : (P > E)) E = P;
    return E;
}

// ---------------------------------------------------------------------------
// K2: one CTA per batch. Fast path: ReLU zeros (normalized <= 0) are first
// in stable ascending argsort, in index order -> stream compaction of the
// first TOPN qualifying indices. Slow path (T < TOPN): radix-select +
// bitonic on 46-bit keys (unreachable for N(0,1) data, kept for correctness).
// ---------------------------------------------------------------------------
__global__ __launch_bounds__(1024) void select_kernel(const float* __restrict__ gamma,
                                                      const float* __restrict__ beta) {
    extern __shared__ unsigned long long dyn[];   // slow path only
    unsigned long long* keys = dyn;               // SEQ
    unsigned long long* sel  = dyn + SEQ;         // TOPN

    __shared__ float red1[512], red2[512];
    __shared__ unsigned warpsum[32];
    __shared__ unsigned warpexcl[32];
    __shared__ unsigned total_s;

    const int tid  = threadIdx.x;
    const int lane = tid & 31;
    const int warp = tid >> 5;
    const int b    = blockIdx.x;

    // --- mean / var from K1 partials (444 entries) ---
    if (tid < 512) {
        float S = (tid < K1_GRID) ? g_psum[tid] : 0.f;
        float Q = (tid < K1_GRID) ? g_psq[tid]  : 0.f;
        red1[tid] = S; red2[tid] = Q;
    }
    __syncthreads();
    for (int off = 256; off > 0; off >>= 1) {
        if (tid < off) { red1[tid] += red1[tid + off]; red2[tid] += red2[tid + off]; }
        __syncthreads();
    }
    float mean = red1[0] / (float)ROWS;
    float var  = red2[0] / (float)ROWS - mean * mean;
    if (var < 0.f) var = 0.f;
    float scale = rsqrtf(var + 1e-5f) * gamma[0];
    float shift = beta[0] - mean * scale;

    // --- fast path: stable compaction of normalized <= 0 ---
    const float* sc = g_score + (size_t)b * SEQ;
    const float4* p4 = (const float4*)(sc + tid * 16);
    unsigned mask16 = 0;
#pragma unroll
    for (int j = 0; j < 4; j++) {
        float4 v = p4[j];
        if (fmaf(v.x, scale, shift) <= 0.f) mask16 |= 1u << (4*j + 0);
        if (fmaf(v.y, scale, shift) <= 0.f) mask16 |= 1u << (4*j + 1);
        if (fmaf(v.z, scale, shift) <= 0.f) mask16 |= 1u << (4*j + 2);
        if (fmaf(v.w, scale, shift) <= 0.f) mask16 |= 1u << (4*j + 3);
    }
    unsigned c = (unsigned)__popc(mask16);

    unsigned incl = c;
#pragma unroll
    for (int off = 1; off < 32; off <<= 1) {
        unsigned n = __shfl_up_sync(0xffffffffu, incl, off);
        if (lane >= off) incl += n;
    }
    if (lane == 31) warpsum[warp] = incl;
    __syncthreads();
    if (tid < 32) {
        unsigned wv = warpsum[tid];
        unsigned wincl = wv;
#pragma unroll
        for (int off = 1; off < 32; off <<= 1) {
            unsigned n = __shfl_up_sync(0xffffffffu, wincl, off);
            if (tid >= off) wincl += n;
        }
        warpexcl[tid] = wincl - wv;
        if (tid == 31) total_s = wincl;
    }
    __syncthreads();
    unsigned T = total_s;

    if (T >= (unsigned)TOPN) {
        unsigned r = warpexcl[warp] + (incl - c);
        if (r < (unsigned)TOPN) {
            unsigned base_i = (unsigned)tid * 16u;
#pragma unroll
            for (int j = 0; j < 16; j++) {
                if (mask16 & (1u << j)) {
                    if (r < (unsigned)TOPN) g_idx[b * TOPN + r] = base_i + j;
                    r++;
                }
            }
        }
        return;
    }

    // ===== slow path (practically unreachable) =====
    __shared__ unsigned hist[256];
    __shared__ unsigned long long prefix_s;
    __shared__ int k_s;
    __shared__ unsigned cnt_s;

    for (int i = tid; i < SEQ; i += 1024) {
        float r = fmaxf(0.f, fmaf(sc[i], scale, shift));
        keys[i] = ((unsigned long long)__float_as_uint(r) << 14) | (unsigned)i;
    }
    if (tid == 0) { prefix_s = 0ULL; k_s = TOPN - 1; cnt_s = 0u; }
    __syncthreads();

    unsigned long long prefix = 0ULL;
#pragma unroll
    for (int d = 5; d >= 0; --d) {
        for (int i = tid; i < 256; i += 1024) hist[i] = 0u;
        __syncthreads();
        const int sh = d * 8;
        const unsigned long long pmask = (d == 5) ? 0ULL : (~0ULL << (sh + 8));
        for (int i = tid; i < SEQ; i += 1024) {
            unsigned long long key = keys[i];
            bool pr = ((key & pmask) == prefix);
            unsigned active = __ballot_sync(0xffffffffu, pr);
            if (pr) {
                unsigned bin = (unsigned)(key >> sh) & 255u;
                unsigned peers = __match_any_sync(active, bin);
                if (lane == __ffs(peers) - 1)
                    atomicAdd(&hist[bin], __popc(peers));
            }
        }
        __syncthreads();
        if (tid < 32) {
            int k = k_s;
            unsigned v[8]; unsigned tot = 0u;
#pragma unroll
            for (int j = 0; j < 8; j++) { v[j] = hist[tid*8 + j]; tot += v[j]; }
            unsigned ex = tot;
#pragma unroll
            for (int off = 1; off < 32; off <<= 1) {
                unsigned n = __shfl_up_sync(0xffffffffu, ex, off);
                if (tid >= off) ex += n;
            }
            ex -= tot;
            if ((unsigned)k >= ex && (unsigned)k < ex + tot) {
                unsigned kk = (unsigned)k - ex;
                int bin = tid * 8;
#pragma unroll
                for (int j = 0; j < 8; j++) {
                    if (kk < v[j]) { bin = tid*8 + j; break; }
                    kk -= v[j];
                }
                prefix_s = prefix | ((unsigned long long)bin << sh);
                k_s = (int)kk;
            }
        }
        __syncthreads();
        prefix = prefix_s;
    }
    const unsigned long long cutoff = prefix;

    for (int i = tid; i < SEQ; i += 1024) {
        unsigned long long key = keys[i];
        bool pr = (key <= cutoff);
        unsigned m = __ballot_sync(0xffffffffu, pr);
        if (pr) {
            int leader = __ffs(m) - 1;
            unsigned base;
            if (lane == leader) base = atomicAdd(&cnt_s, (unsigned)__popc(m));
            base = __shfl_sync(m, base, leader);
            sel[base + __popc(m & ((1u << lane) - 1u))] = key;
        }
    }
    __syncthreads();

    unsigned long long E0 = sel[tid];
    unsigned long long E1 = sel[tid + 1024];
#pragma unroll
    for (int k = 2; k <= 32; k <<= 1)
#pragma unroll
        for (int j = k >> 1; j >= 1; j >>= 1) {
            E0 = cex_shfl(E0, tid, j, k);
            E1 = cex_shfl(E1, tid + 1024, j, k);
        }
#pragma unroll
    for (int k = 64; k <= 1024; k <<= 1) {
        __syncthreads();
        sel[tid] = E0; sel[tid + 1024] = E1;
        __syncthreads();
        for (int j = k >> 1; j >= 32; j >>= 1) {
            int idx = ((tid & ~(j - 1)) << 1) | (tid & (j - 1));
            int l = idx | j;
            unsigned long long a = sel[idx], cc = sel[l];
            bool asc = ((idx & k) == 0);
            if ((a > cc) == asc) { sel[idx] = cc; sel[l] = a; }
            __syncthreads();
        }
        E0 = sel[tid]; E1 = sel[tid + 1024];
#pragma unroll
        for (int j = 16; j >= 1; j >>= 1) {
            E0 = cex_shfl(E0, tid, j, k);
            E1 = cex_shfl(E1, tid + 1024, j, k);
        }
    }
    {
        const int k = 2048;
        if (E0 > E1) { unsigned long long t = E0; E0 = E1; E1 = t; }
        __syncthreads();
        sel[tid] = E0; sel[tid + 1024] = E1;
        __syncthreads();
        for (int j = 512; j >= 32; j >>= 1) {
            int idx = ((tid & ~(j - 1)) << 1) | (tid & (j - 1));
            int l = idx | j;
            unsigned long long a = sel[idx], cc = sel[l];
            if (a > cc) { sel[idx] = cc; sel[l] = a; }
            __syncthreads();
        }
        E0 = sel[tid]; E1 = sel[tid + 1024];
#pragma unroll
        for (int j = 16; j >= 1; j >>= 1) {
            E0 = cex_shfl(E0, tid, j, k);
            E1 = cex_shfl(E1, tid + 1024, j, k);
        }
    }
    g_idx[b * TOPN + tid]        = (unsigned)(E0 & 0x3fffu);
    g_idx[b * TOPN + tid + 1024] = (unsigned)(E1 & 0x3fffu);
}

// ---------------------------------------------------------------------------
// K3: gather rows: out[b, r, :] = x_select[b, idx[b,r], :]
// 512 threads / 8 rows per block, streaming loads + stores.
// ---------------------------------------------------------------------------
__global__ __launch_bounds__(512) void gather_kernel(const float* __restrict__ xs,
                                                     float* __restrict__ out) {
    int rid  = blockIdx.x * 8 + (threadIdx.x >> 6);   // 0 .. BATCH*TOPN-1
    int lane = threadIdx.x & 63;
    int b    = rid >> 11;                              // TOPN == 2048
    unsigned idx = g_idx[rid];
    const float4* src = (const float4*)(xs + ((size_t)b * SEQ + idx) * CH);
    float4* dst = (float4*)(out + (size_t)rid * CH);
    __stcs(dst + lane, __ldcs(src + lane));
}

// ---------------------------------------------------------------------------
extern "C" void kernel_launch(void* const* d_in, const int* in_sizes, int n_in,
                              void* d_out, int out_size) {
    const float* x_in  = (const float*)d_in[0];
    const float* x_sel = (const float*)d_in[1];
    const float* w     = (const float*)d_in[2];
    const float* bias  = (const float*)d_in[3];
    const float* gamma = (const float*)d_in[4];
    const float* beta  = (const float*)d_in[5];
    float* out = (float*)d_out;

    const int sel_smem = (SEQ + TOPN) * (int)sizeof(unsigned long long);  // 147456
    cudaFuncSetAttribute(select_kernel,
                         cudaFuncAttributeMaxDynamicSharedMemorySize, sel_smem);

    score_kernel<<<K1_GRID, K1_THREADS>>>(x_in, w, bias);
    select_kernel<<<BATCH, 1024, sel_smem>>>(gamma, beta);
    gather_kernel<<<(BATCH * TOPN) / 8, 512>>>(x_sel, out);
}

// round 7
// speedup vs baseline: 1.7046x; 1.0508x over previous
#include <cuda_runtime.h>

static constexpr int BATCH = 8;
static constexpr int SEQ   = 16384;
static constexpr int CH    = 256;
static constexpr int TOPN  = 2048;
static constexpr int ROWS  = BATCH * SEQ;     // 131072
static constexpr int QUADS = ROWS / 4;        // 32768

static constexpr int K1_GRID    = 444;        // 148 SMs * 3 resident CTAs
static constexpr int K1_THREADS = 256;        // 8 warps
static constexpr int K1_WARPS_TOTAL = K1_GRID * (K1_THREADS / 32);  // 3552

__device__ float g_score[ROWS];
__device__ float g_psum[K1_GRID];
__device__ float g_psq[K1_GRID];
__device__ unsigned g_idx[BATCH * TOPN];

// ---------------------------------------------------------------------------
// K1: persistent grid-stride. A warp covers 4 rows, 8 lanes per row
// (lane = 8*subrow + pos). 8 front-batched float4 streaming loads per thread
// (each LDG: 4 x 128B contiguous segments -> fully coalesced). Weight held
// loop-invariant in registers. Row reduce = 3-step shfl butterfly within each
// 8-lane group -- all 4 rows reduce simultaneously in ONE register.
// ---------------------------------------------------------------------------
__global__ __launch_bounds__(K1_THREADS, 3) void score_kernel(const float* __restrict__ x,
                                                              const float* __restrict__ w,
                                                              const float* __restrict__ bias) {
    const int warp   = threadIdx.x >> 5;
    const int lane   = threadIdx.x & 31;
    const int subrow = lane >> 3;     // 0..3 : which of the warp's 4 rows
    const int pos    = lane & 7;      // 0..7 : position within the row
    const int gw     = blockIdx.x * (K1_THREADS / 32) + warp;

    const float4* wv = (const float4*)w;
    float4 W[8];
#pragma unroll
    for (int j = 0; j < 8; j++) W[j] = wv[pos + 8*j];   // loop-invariant
    const float bb = bias[0];

    float S = 0.f, Q = 0.f;

    for (int quad = gw; quad < QUADS; quad += K1_WARPS_TOTAL) {
        const size_t row = (size_t)quad * 4 + subrow;
        const float4* xb = (const float4*)(x + row * CH);   // 64 float4 per row

        float4 v[8];
#pragma unroll
        for (int j = 0; j < 8; j++) v[j] = __ldcs(xb + pos + 8*j);

        float d = 0.f;
#pragma unroll
        for (int j = 0; j < 8; j++)
            d += v[j].x*W[j].x + v[j].y*W[j].y + v[j].z*W[j].z + v[j].w*W[j].w;

        // reduce within each 8-lane group (4 rows simultaneously)
        d += __shfl_xor_sync(0xffffffffu, d, 4);
        d += __shfl_xor_sync(0xffffffffu, d, 2);
        d += __shfl_xor_sync(0xffffffffu, d, 1);

        if (pos == 0) {                 // lanes 0,8,16,24 -> 4 consecutive rows
            float c = d + bb;
            __stcs(&g_score[row], c);
            S += c;
            Q += c * c;
        }
    }

    // block reduction of S, Q
#pragma unroll
    for (int off = 16; off > 0; off >>= 1) {
        S += __shfl_xor_sync(0xffffffffu, S, off);
        Q += __shfl_xor_sync(0xffffffffu, Q, off);
    }
    __shared__ float ws[K1_THREADS / 32], wq[K1_THREADS / 32];
    if (lane == 0) { ws[warp] = S; wq[warp] = Q; }
    __syncthreads();
    if (threadIdx.x < 32) {
        float s = (threadIdx.x < K1_THREADS / 32) ? ws[threadIdx.x] : 0.f;
        float q = (threadIdx.x < K1_THREADS / 32) ? wq[threadIdx.x] : 0.f;
#pragma unroll
        for (int off = 4; off > 0; off >>= 1) {
            s += __shfl_xor_sync(0xffffffffu, s, off);
            q += __shfl_xor_sync(0xffffffffu, q, off);
        }
        if (threadIdx.x == 0) { g_psum[blockIdx.x] = s; g_psq[blockIdx.x] = q; }
    }
}

// ---------------------------------------------------------------------------
// Bitonic helper for the (practically never taken) slow path
// ---------------------------------------------------------------------------
__device__ __forceinline__ unsigned long long cex_shfl(unsigned long long E,
                                                       int i, int j, int k) {
    unsigned long long P = __shfl_xor_sync(0xffffffffu, E, j);
    bool takeMin = (((i & j) == 0) == ((i & k) == 0));
    if (takeMin ? (P < E) : (P > E)) E = P;
    return E;
}

// ---------------------------------------------------------------------------
// K2: one CTA per batch. Fast path: ReLU zeros (normalized <= 0) are first
// in stable ascending argsort, in index order -> stream compaction of the
// first TOPN qualifying indices. Slow path (T < TOPN): radix-select +
// bitonic on 46-bit keys (unreachable for N(0,1) data, kept for correctness).
// ---------------------------------------------------------------------------
__global__ __launch_bounds__(1024) void select_kernel(const float* __restrict__ gamma,
                                                      const float* __restrict__ beta) {
    extern __shared__ unsigned long long dyn[];   // slow path only
    unsigned long long* keys = dyn;               // SEQ
    unsigned long long* sel  = dyn + SEQ;         // TOPN

    __shared__ float red1[512], red2[512];
    __shared__ unsigned warpsum[32];
    __shared__ unsigned warpexcl[32];
    __shared__ unsigned total_s;

    const int tid  = threadIdx.x;
    const int lane = tid & 31;
    const int warp = tid >> 5;
    const int b    = blockIdx.x;

    // --- mean / var from K1 partials (K1_GRID entries) ---
    if (tid < 512) {
        float S = (tid < K1_GRID) ? g_psum[tid] : 0.f;
        float Q = (tid < K1_GRID) ? g_psq[tid]  : 0.f;
        red1[tid] = S; red2[tid] = Q;
    }
    __syncthreads();
    for (int off = 256; off > 0; off >>= 1) {
        if (tid < off) { red1[tid] += red1[tid + off]; red2[tid] += red2[tid + off]; }
        __syncthreads();
    }
    float mean = red1[0] / (float)ROWS;
    float var  = red2[0] / (float)ROWS - mean * mean;
    if (var < 0.f) var = 0.f;
    float scale = rsqrtf(var + 1e-5f) * gamma[0];
    float shift = beta[0] - mean * scale;

    // --- fast path: stable compaction of normalized <= 0 ---
    const float* sc = g_score + (size_t)b * SEQ;
    const float4* p4 = (const float4*)(sc + tid * 16);
    unsigned mask16 = 0;
#pragma unroll
    for (int j = 0; j < 4; j++) {
        float4 v = p4[j];
        if (fmaf(v.x, scale, shift) <= 0.f) mask16 |= 1u << (4*j + 0);
        if (fmaf(v.y, scale, shift) <= 0.f) mask16 |= 1u << (4*j + 1);
        if (fmaf(v.z, scale, shift) <= 0.f) mask16 |= 1u << (4*j + 2);
        if (fmaf(v.w, scale, shift) <= 0.f) mask16 |= 1u << (4*j + 3);
    }
    unsigned c = (unsigned)__popc(mask16);

    unsigned incl = c;
#pragma unroll
    for (int off = 1; off < 32; off <<= 1) {
        unsigned n = __shfl_up_sync(0xffffffffu, incl, off);
        if (lane >= off) incl += n;
    }
    if (lane == 31) warpsum[warp] = incl;
    __syncthreads();
    if (tid < 32) {
        unsigned wv = warpsum[tid];
        unsigned wincl = wv;
#pragma unroll
        for (int off = 1; off < 32; off <<= 1) {
            unsigned n = __shfl_up_sync(0xffffffffu, wincl, off);
            if (tid >= off) wincl += n;
        }
        warpexcl[tid] = wincl - wv;
        if (tid == 31) total_s = wincl;
    }
    __syncthreads();
    unsigned T = total_s;

    if (T >= (unsigned)TOPN) {
        unsigned r = warpexcl[warp] + (incl - c);
        if (r < (unsigned)TOPN) {
            unsigned base_i = (unsigned)tid * 16u;
#pragma unroll
            for (int j = 0; j < 16; j++) {
                if (mask16 & (1u << j)) {
                    if (r < (unsigned)TOPN) g_idx[b * TOPN + r] = base_i + j;
                    r++;
                }
            }
        }
        return;
    }

    // ===== slow path (practically unreachable) =====
    __shared__ unsigned hist[256];
    __shared__ unsigned long long prefix_s;
    __shared__ int k_s;
    __shared__ unsigned cnt_s;

    for (int i = tid; i < SEQ; i += 1024) {
        float r = fmaxf(0.f, fmaf(sc[i], scale, shift));
        keys[i] = ((unsigned long long)__float_as_uint(r) << 14) | (unsigned)i;
    }
    if (tid == 0) { prefix_s = 0ULL; k_s = TOPN - 1; cnt_s = 0u; }
    __syncthreads();

    unsigned long long prefix = 0ULL;
#pragma unroll
    for (int d = 5; d >= 0; --d) {
        for (int i = tid; i < 256; i += 1024) hist[i] = 0u;
        __syncthreads();
        const int sh = d * 8;
        const unsigned long long pmask = (d == 5) ? 0ULL : (~0ULL << (sh + 8));
        for (int i = tid; i < SEQ; i += 1024) {
            unsigned long long key = keys[i];
            bool pr = ((key & pmask) == prefix);
            unsigned active = __ballot_sync(0xffffffffu, pr);
            if (pr) {
                unsigned bin = (unsigned)(key >> sh) & 255u;
                unsigned peers = __match_any_sync(active, bin);
                if (lane == __ffs(peers) - 1)
                    atomicAdd(&hist[bin], __popc(peers));
            }
        }
        __syncthreads();
        if (tid < 32) {
            int k = k_s;
            unsigned v[8]; unsigned tot = 0u;
#pragma unroll
            for (int j = 0; j < 8; j++) { v[j] = hist[tid*8 + j]; tot += v[j]; }
            unsigned ex = tot;
#pragma unroll
            for (int off = 1; off < 32; off <<= 1) {
                unsigned n = __shfl_up_sync(0xffffffffu, ex, off);
                if (tid >= off) ex += n;
            }
            ex -= tot;
            if ((unsigned)k >= ex && (unsigned)k < ex + tot) {
                unsigned kk = (unsigned)k - ex;
                int bin = tid * 8;
#pragma unroll
                for (int j = 0; j < 8; j++) {
                    if (kk < v[j]) { bin = tid*8 + j; break; }
                    kk -= v[j];
                }
                prefix_s = prefix | ((unsigned long long)bin << sh);
                k_s = (int)kk;
            }
        }
        __syncthreads();
        prefix = prefix_s;
    }
    const unsigned long long cutoff = prefix;

    for (int i = tid; i < SEQ; i += 1024) {
        unsigned long long key = keys[i];
        bool pr = (key <= cutoff);
        unsigned m = __ballot_sync(0xffffffffu, pr);
        if (pr) {
            int leader = __ffs(m) - 1;
            unsigned base;
            if (lane == leader) base = atomicAdd(&cnt_s, (unsigned)__popc(m));
            base = __shfl_sync(m, base, leader);
            sel[base + __popc(m & ((1u << lane) - 1u))] = key;
        }
    }
    __syncthreads();

    unsigned long long E0 = sel[tid];
    unsigned long long E1 = sel[tid + 1024];
#pragma unroll
    for (int k = 2; k <= 32; k <<= 1)
#pragma unroll
        for (int j = k >> 1; j >= 1; j >>= 1) {
            E0 = cex_shfl(E0, tid, j, k);
            E1 = cex_shfl(E1, tid + 1024, j, k);
        }
#pragma unroll
    for (int k = 64; k <= 1024; k <<= 1) {
        __syncthreads();
        sel[tid] = E0; sel[tid + 1024] = E1;
        __syncthreads();
        for (int j = k >> 1; j >= 32; j >>= 1) {
            int idx = ((tid & ~(j - 1)) << 1) | (tid & (j - 1));
            int l = idx | j;
            unsigned long long a = sel[idx], cc = sel[l];
            bool asc = ((idx & k) == 0);
            if ((a > cc) == asc) { sel[idx] = cc; sel[l] = a; }
            __syncthreads();
        }
        E0 = sel[tid]; E1 = sel[tid + 1024];
#pragma unroll
        for (int j = 16; j >= 1; j >>= 1) {
            E0 = cex_shfl(E0, tid, j, k);
            E1 = cex_shfl(E1, tid + 1024, j, k);
        }
    }
    {
        const int k = 2048;
        if (E0 > E1) { unsigned long long t = E0; E0 = E1; E1 = t; }
        __syncthreads();
        sel[tid] = E0; sel[tid + 1024] = E1;
        __syncthreads();
        for (int j = 512; j >= 32; j >>= 1) {
            int idx = ((tid & ~(j - 1)) << 1) | (tid & (j - 1));
            int l = idx | j;
            unsigned long long a = sel[idx], cc = sel[l];
            if (a > cc) { sel[idx] = cc; sel[l] = a; }
            __syncthreads();
        }
        E0 = sel[tid]; E1 = sel[tid + 1024];
#pragma unroll
        for (int j = 16; j >= 1; j >>= 1) {
            E0 = cex_shfl(E0, tid, j, k);
            E1 = cex_shfl(E1, tid + 1024, j, k);
        }
    }
    g_idx[b * TOPN + tid]        = (unsigned)(E0 & 0x3fffu);
    g_idx[b * TOPN + tid + 1024] = (unsigned)(E1 & 0x3fffu);
}

// ---------------------------------------------------------------------------
// K3: gather rows: out[b, r, :] = x_select[b, idx[b,r], :]
// ---------------------------------------------------------------------------
__global__ __launch_bounds__(512) void gather_kernel(const float* __restrict__ xs,
                                                     float* __restrict__ out) {
    int rid  = blockIdx.x * 8 + (threadIdx.x >> 6);   // 0 .. BATCH*TOPN-1
    int lane = threadIdx.x & 63;
    int b    = rid >> 11;                              // TOPN == 2048
    unsigned idx = g_idx[rid];
    const float4* src = (const float4*)(xs + ((size_t)b * SEQ + idx) * CH);
    float4* dst = (float4*)(out + (size_t)rid * CH);
    __stcs(dst + lane, __ldcs(src + lane));
}

// ---------------------------------------------------------------------------
extern "C" void kernel_launch(void* const* d_in, const int* in_sizes, int n_in,
                              void* d_out, int out_size) {
    const float* x_in  = (const float*)d_in[0];
    const float* x_sel = (const float*)d_in[1];
    const float* w     = (const float*)d_in[2];
    const float* bias  = (const float*)d_in[3];
    const float* gamma = (const float*)d_in[4];
    const float* beta  = (const float*)d_in[5];
    float* out = (float*)d_out;

    const int sel_smem = (SEQ + TOPN) * (int)sizeof(unsigned long long);  // 147456
    cudaFuncSetAttribute(select_kernel,
                         cudaFuncAttributeMaxDynamicSharedMemorySize, sel_smem);

    score_kernel<<<K1_GRID, K1_THREADS>>>(x_in, w, bias);
    select_kernel<<<BATCH, 1024, sel_smem>>>(gamma, beta);
    gather_kernel<<<(BATCH * TOPN) / 8, 512>>>(x_sel, out);
}